// round 8
// baseline (speedup 1.0000x reference)
#include <cuda_runtime.h>

#define BB 32
#define TT 1024
#define NN 128
#define RBLK 4                      // row-blocks per batch -> 128 CTAs
#define ROWS 32                     // rows per CTA
#define THREADS 128
#define TR 4                        // rows per thread
#define TC 8                        // cols per thread
#define LANES 16
#define CHUNK 32
#define NCHUNK (TT / CHUNK)

// pbuf in u64 units: [step][q][lane][rr]
#define PBQ 68                      // u64 stride per q (64 + 4 pad -> 2-way max conflict)
#define PBS 544                     // u64 stride per step (8*68)

// smem layout (float offsets)
#define SM_XS     0
#define SM_PBUF   8192                              // 2*CHUNK*NN floats of xs
#define SM_SCOEF  (SM_PBUF + CHUNK * PBS * 2)       // pbuf = 34816 floats
#define SM_CSCALE (SM_SCOEF + TT + 2)
#define SM_CFOLD  (SM_CSCALE + TT)
#define SM_APOW   (SM_CFOLD + NCHUNK)
#define SM_APOWI  (SM_APOW + CHUNK + 1)
#define SM_MBITS  (SM_APOWI + CHUNK + 1)
#define SM_FLOATS (SM_MBITS + NCHUNK)
#define SM_BYTES  (SM_FLOATS * 4)                   // ~180.8 KB

typedef unsigned long long u64;

// ---------- packed f32x2 helpers ----------
__device__ __forceinline__ u64 pack2(float lo, float hi) {
    u64 r; asm("mov.b64 %0, {%1, %2};" : "=l"(r) : "f"(lo), "f"(hi)); return r;
}
__device__ __forceinline__ void unpack2(u64 v, float& lo, float& hi) {
    asm("mov.b64 {%0, %1}, %2;" : "=f"(lo), "=f"(hi) : "l"(v));
}
__device__ __forceinline__ u64 fma2(u64 a, u64 b, u64 c) {
    u64 d; asm("fma.rn.f32x2 %0, %1, %2, %3;" : "=l"(d) : "l"(a), "l"(b), "l"(c)); return d;
}
__device__ __forceinline__ u64 mul2(u64 a, u64 b) {
    u64 d; asm("mul.rn.f32x2 %0, %1, %2;" : "=l"(d) : "l"(a), "l"(b)); return d;
}
__device__ __forceinline__ u64 add2(u64 a, u64 b) {
    u64 d; asm("add.rn.f32x2 %0, %1, %2;" : "=l"(d) : "l"(a), "l"(b)); return d;
}

// ---------- cp.async ----------
__device__ __forceinline__ void cpasync16(void* s, const void* g) {
    unsigned saddr = (unsigned)__cvta_generic_to_shared(s);
    asm volatile("cp.async.cg.shared.global [%0], [%1], 16;" :: "r"(saddr), "l"(g));
}
// 4096 floats per chunk / 128 threads = 32 floats = 8 x 16B each
__device__ __forceinline__ void load_chunk(float* dst, const float* src, int tid) {
    #pragma unroll
    for (int i = 0; i < 8; i++) {
        int off = (tid + i * THREADS) * 4;
        cpasync16(dst + off, src + off);
    }
}

__global__ __launch_bounds__(THREADS, 1)
void bdh_scan_kernel(const float* __restrict__ x,
                     const float* __restrict__ w_init,
                     const float* __restrict__ alpha_p,
                     const float* __restrict__ eta_p,
                     const int*   __restrict__ mask,
                     float* __restrict__ w_out,
                     float* __restrict__ y_out)
{
    extern __shared__ float smem[];
    float*    xs     = smem + SM_XS;
    u64*      pbuf   = reinterpret_cast<u64*>(smem + SM_PBUF);
    float*    scoef  = smem + SM_SCOEF;
    float*    cscale = smem + SM_CSCALE;
    float*    cfold  = smem + SM_CFOLD;
    float*    apow   = smem + SM_APOW;
    float*    apowi  = smem + SM_APOWI;
    unsigned* mbits  = (unsigned*)(smem + SM_MBITS);

    const int b    = blockIdx.x;
    const int rb   = blockIdx.y;
    const int tid  = threadIdx.x;
    const int q    = tid >> 4;            // 0..7
    const int lane = tid & 15;            // 0..15
    const int r0l  = q * TR;              // local first row
    const int r0   = rb * ROWS + r0l;     // global first row
    const int cseg = lane * TC;
    const int tslot = q * PBQ + lane * 4; // u64 offset of this thread's 4 rows

    const float alpha = alpha_p[0];
    const float eta   = eta_p[0];
    const float inva  = 1.0f / alpha;

    const float* xb = x + (size_t)b * TT * NN;
    float* yb = y_out + (size_t)b * TT * NN;

    // prefetch first two x chunks
    load_chunk(xs, xb, tid);
    asm volatile("cp.async.commit_group;");
    load_chunk(xs + CHUNK * NN, xb + CHUNK * NN, tid);
    asm volatile("cp.async.commit_group;");

    // W tile: 4 rows x 8 cols = 16 packed f32x2
    u64 w2[TR][4];
    {
        const float* wb = w_init + (size_t)b * NN * NN + (size_t)r0 * NN + cseg;
        #pragma unroll
        for (int i = 0; i < TR; i++) {
            const ulonglong2* ws = reinterpret_cast<const ulonglong2*>(wb + i * NN);
            ulonglong2 v0 = ws[0], v1 = ws[1];
            w2[i][0] = v0.x; w2[i][1] = v0.y; w2[i][2] = v1.x; w2[i][3] = v1.y;
        }
    }

    // ---- setup: mask bits + power tables + per-step coefficients ----
    {
        const int l32 = tid & 31, wi = tid >> 5;
        for (int ckk = wi; ckk < NCHUNK; ckk += 4) {
            int m = mask[(size_t)b * TT + ckk * 32 + l32];
            unsigned bits = __ballot_sync(0xffffffffu, m != 0);
            if (l32 == 0) mbits[ckk] = bits;
        }
    }
    if (tid == 0) {
        float p = 1.0f, pi = 1.0f;
        #pragma unroll
        for (int k = 0; k <= CHUNK; k++) {
            apow[k] = p;  apowi[k] = pi;
            p *= alpha;   pi *= inva;
        }
    }
    __syncthreads();
    #pragma unroll
    for (int k = 0; k < 8; k++) {
        const int e = tid + k * THREADS;      // 0..1023
        const int ckk = e >> 5, tl = e & 31;
        const unsigned mb = mbits[ckk];
        const int cnt = __popc(mb & ((1u << tl) - 1u));
        cscale[e] = apow[cnt];
        scoef[e]  = ((mb >> tl) & 1u) ? (eta * apowi[cnt + 1]) : 0.0f;
    }
    if (tid < NCHUNK) cfold[tid] = apow[__popc(mbits[tid])];
    if (tid < 2) scoef[TT + tid] = 0.0f;      // over-read pad
    __syncthreads();

    for (int ck = 0; ck < NCHUNK; ck++) {
        asm volatile("cp.async.wait_group 1;");
        __syncthreads();

        const float* xch = xs + (ck & 1) * (CHUNK * NN);
        const float* scp = scoef + ck * CHUNK;

        // ---- initial prefetch for block 0 (steps 0,1) ----
        ulonglong2 A01 = reinterpret_cast<const ulonglong2*>(xch + cseg)[0];
        ulonglong2 A23 = reinterpret_cast<const ulonglong2*>(xch + cseg)[1];
        ulonglong2 B01 = reinterpret_cast<const ulonglong2*>(xch + NN + cseg)[0];
        ulonglong2 B23 = reinterpret_cast<const ulonglong2*>(xch + NN + cseg)[1];
        float4 xrA = *reinterpret_cast<const float4*>(xch + rb * ROWS + r0l);
        float4 xrB = *reinterpret_cast<const float4*>(xch + NN + rb * ROWS + r0l);
        float2 sc  = *reinterpret_cast<const float2*>(scp);

        #pragma unroll 8
        for (int j = 0; j < CHUNK / 2; j++) {
            const u64 a0 = A01.x, a1 = A01.y, a2 = A23.x, a3 = A23.y;
            const u64 b0 = B01.x, b1 = B01.y, b2 = B23.x, b3 = B23.y;
            const float4 xa = xrA, xb4 = xrB;
            const float sA = sc.x, sB = sc.y;

            // prefetch next block (j==15 over-reads into pbuf/pad region; unused)
            const float* xn0 = xch + (2 * j + 2) * NN;
            A01 = reinterpret_cast<const ulonglong2*>(xn0 + cseg)[0];
            A23 = reinterpret_cast<const ulonglong2*>(xn0 + cseg)[1];
            B01 = reinterpret_cast<const ulonglong2*>(xn0 + NN + cseg)[0];
            B23 = reinterpret_cast<const ulonglong2*>(xn0 + NN + cseg)[1];
            xrA = *reinterpret_cast<const float4*>(xn0 + rb * ROWS + r0l);
            xrB = *reinterpret_cast<const float4*>(xn0 + NN + rb * ROWS + r0l);
            sc  = *reinterpret_cast<const float2*>(scp + 2 * j + 2);

            // dots vs pre-update U: P (step t), Q (step t+1)
            u64 P0 = mul2(w2[0][0], a0); u64 Q0 = mul2(w2[0][0], b0);
            u64 P1 = mul2(w2[1][0], a0); u64 Q1 = mul2(w2[1][0], b0);
            u64 P2 = mul2(w2[2][0], a0); u64 Q2 = mul2(w2[2][0], b0);
            u64 P3 = mul2(w2[3][0], a0); u64 Q3 = mul2(w2[3][0], b0);
            P0 = fma2(w2[0][1], a1, P0); Q0 = fma2(w2[0][1], b1, Q0);
            P1 = fma2(w2[1][1], a1, P1); Q1 = fma2(w2[1][1], b1, Q1);
            P2 = fma2(w2[2][1], a1, P2); Q2 = fma2(w2[2][1], b1, Q2);
            P3 = fma2(w2[3][1], a1, P3); Q3 = fma2(w2[3][1], b1, Q3);
            P0 = fma2(w2[0][2], a2, P0); Q0 = fma2(w2[0][2], b2, Q0);
            P1 = fma2(w2[1][2], a2, P1); Q1 = fma2(w2[1][2], b2, Q1);
            P2 = fma2(w2[2][2], a2, P2); Q2 = fma2(w2[2][2], b2, Q2);
            P3 = fma2(w2[3][2], a2, P3); Q3 = fma2(w2[3][2], b2, Q3);
            P0 = fma2(w2[0][3], a3, P0); Q0 = fma2(w2[0][3], b3, Q0);
            P1 = fma2(w2[1][3], a3, P1); Q1 = fma2(w2[1][3], b3, Q1);
            P2 = fma2(w2[2][3], a3, P2); Q2 = fma2(w2[2][3], b3, Q2);
            P3 = fma2(w2[3][3], a3, P3); Q3 = fma2(w2[3][3], b3, Q3);

            // cross term d = xv_t . xv_{t+1} (thread-column partial, packed)
            u64 d = mul2(a0, b0);
            d = fma2(a1, b1, d);
            d = fma2(a2, b2, d);
            d = fma2(a3, b3, d);

            // step-t gains
            const float gA0f = sA * xa.x, gA1f = sA * xa.y;
            const float gA2f = sA * xa.z, gA3f = sA * xa.w;
            const u64 gA0 = pack2(gA0f, gA0f), gA1 = pack2(gA1f, gA1f);
            const u64 gA2 = pack2(gA2f, gA2f), gA3 = pack2(gA3f, gA3f);

            // correct step t+1 dots for the (possibly zero) step-t update
            Q0 = fma2(gA0, d, Q0);
            Q1 = fma2(gA1, d, Q1);
            Q2 = fma2(gA2, d, Q2);
            Q3 = fma2(gA3, d, Q3);

            // store packed partials (finalized in bulk reduce)
            u64* st0 = pbuf + (2 * j) * PBS + tslot;
            ulonglong2 s0a; s0a.x = P0; s0a.y = P1;
            ulonglong2 s0b; s0b.x = P2; s0b.y = P3;
            reinterpret_cast<ulonglong2*>(st0)[0] = s0a;
            reinterpret_cast<ulonglong2*>(st0)[1] = s0b;
            u64* st1 = st0 + PBS;
            ulonglong2 s1a; s1a.x = Q0; s1a.y = Q1;
            ulonglong2 s1b; s1b.x = Q2; s1b.y = Q3;
            reinterpret_cast<ulonglong2*>(st1)[0] = s1a;
            reinterpret_cast<ulonglong2*>(st1)[1] = s1b;

            // fused updates: U += gA (x) xv_t + gB (x) xv_{t+1}
            w2[0][0] = fma2(gA0, a0, w2[0][0]);
            w2[0][1] = fma2(gA0, a1, w2[0][1]);
            w2[0][2] = fma2(gA0, a2, w2[0][2]);
            w2[0][3] = fma2(gA0, a3, w2[0][3]);
            w2[1][0] = fma2(gA1, a0, w2[1][0]);
            w2[1][1] = fma2(gA1, a1, w2[1][1]);
            w2[1][2] = fma2(gA1, a2, w2[1][2]);
            w2[1][3] = fma2(gA1, a3, w2[1][3]);
            w2[2][0] = fma2(gA2, a0, w2[2][0]);
            w2[2][1] = fma2(gA2, a1, w2[2][1]);
            w2[2][2] = fma2(gA2, a2, w2[2][2]);
            w2[2][3] = fma2(gA2, a3, w2[2][3]);
            w2[3][0] = fma2(gA3, a0, w2[3][0]);
            w2[3][1] = fma2(gA3, a1, w2[3][1]);
            w2[3][2] = fma2(gA3, a2, w2[3][2]);
            w2[3][3] = fma2(gA3, a3, w2[3][3]);

            const float gB0f = sB * xb4.x, gB1f = sB * xb4.y;
            const float gB2f = sB * xb4.z, gB3f = sB * xb4.w;
            const u64 gB0 = pack2(gB0f, gB0f), gB1 = pack2(gB1f, gB1f);
            const u64 gB2 = pack2(gB2f, gB2f), gB3 = pack2(gB3f, gB3f);
            w2[0][0] = fma2(gB0, b0, w2[0][0]);
            w2[0][1] = fma2(gB0, b1, w2[0][1]);
            w2[0][2] = fma2(gB0, b2, w2[0][2]);
            w2[0][3] = fma2(gB0, b3, w2[0][3]);
            w2[1][0] = fma2(gB1, b0, w2[1][0]);
            w2[1][1] = fma2(gB1, b1, w2[1][1]);
            w2[1][2] = fma2(gB1, b2, w2[1][2]);
            w2[1][3] = fma2(gB1, b3, w2[1][3]);
            w2[2][0] = fma2(gB2, b0, w2[2][0]);
            w2[2][1] = fma2(gB2, b1, w2[2][1]);
            w2[2][2] = fma2(gB2, b2, w2[2][2]);
            w2[2][3] = fma2(gB2, b3, w2[2][3]);
            w2[3][0] = fma2(gB3, b0, w2[3][0]);
            w2[3][1] = fma2(gB3, b1, w2[3][1]);
            w2[3][2] = fma2(gB3, b2, w2[3][2]);
            w2[3][3] = fma2(gB3, b3, w2[3][3]);
        }

        // unconditional decay fold
        {
            const float cf = cfold[ck];
            const u64 c2 = pack2(cf, cf);
            #pragma unroll
            for (int i = 0; i < TR; i++)
                #pragma unroll
                for (int k = 0; k < 4; k++) w2[i][k] = mul2(w2[i][k], c2);
        }

        __syncthreads();   // partials visible; x buffer free

        const int nk = ck + 2;
        if (nk < NCHUNK)
            load_chunk(xs + (ck & 1) * (CHUNK * NN), xb + (size_t)nk * CHUNK * NN, tid);
        asm volatile("cp.async.commit_group;");

        // ---- bulk reduction: 1024 tasks (step, row), 8 per thread ----
        #pragma unroll
        for (int o = 0; o < 8; o++) {
            const int id = tid + o * THREADS;
            const int s  = id >> 5;           // step in chunk
            const int r  = id & 31;           // local row
            const u64* pp = pbuf + s * PBS + (r >> 2) * PBQ + (r & 3);
            u64 x0 = add2(pp[0 * 4],  pp[1 * 4]);
            u64 x1 = add2(pp[2 * 4],  pp[3 * 4]);
            u64 x2 = add2(pp[4 * 4],  pp[5 * 4]);
            u64 x3 = add2(pp[6 * 4],  pp[7 * 4]);
            x0 = add2(x0, add2(pp[8 * 4],  pp[9 * 4]));
            x1 = add2(x1, add2(pp[10 * 4], pp[11 * 4]));
            x2 = add2(x2, add2(pp[12 * 4], pp[13 * 4]));
            x3 = add2(x3, add2(pp[14 * 4], pp[15 * 4]));
            u64 acc = add2(add2(x0, x1), add2(x2, x3));
            float lo, hi; unpack2(acc, lo, hi);
            yb[(size_t)(ck * CHUNK + s) * NN + rb * ROWS + r] =
                (lo + hi) * cscale[ck * CHUNK + s];
        }
        // next top __syncthreads orders pbuf reads before overwrite
    }

    // ---- final W ----
    {
        float* wb = w_out + (size_t)b * NN * NN + (size_t)r0 * NN + cseg;
        #pragma unroll
        for (int i = 0; i < TR; i++) {
            ulonglong2 v0, v1;
            v0.x = w2[i][0]; v0.y = w2[i][1];
            v1.x = w2[i][2]; v1.y = w2[i][3];
            reinterpret_cast<ulonglong2*>(wb + i * NN)[0] = v0;
            reinterpret_cast<ulonglong2*>(wb + i * NN)[1] = v1;
        }
    }
}

extern "C" void kernel_launch(void* const* d_in, const int* in_sizes, int n_in,
                              void* d_out, int out_size) {
    const float* x      = (const float*)d_in[0];
    const float* w_init = (const float*)d_in[1];
    const float* alpha  = (const float*)d_in[2];
    const float* eta    = (const float*)d_in[3];
    const int*   mask   = (const int*)d_in[4];

    float* w_out = (float*)d_out;
    float* y_out = (float*)d_out + (size_t)BB * NN * NN;

    static bool attr_set = false;
    if (!attr_set) {
        cudaFuncSetAttribute(bdh_scan_kernel,
                             cudaFuncAttributeMaxDynamicSharedMemorySize, SM_BYTES);
        attr_set = true;
    }

    dim3 grid(BB, RBLK);
    bdh_scan_kernel<<<grid, THREADS, SM_BYTES>>>(x, w_init, alpha, eta, mask,
                                                 w_out, y_out);
}

// round 9
// speedup vs baseline: 1.5109x; 1.5109x over previous
#include <cuda_runtime.h>

#define BB 32
#define TT 1024
#define NN 128
#define RBLK 4                      // row-blocks per batch -> 128 CTAs
#define ROWS 32                     // rows per CTA
#define THREADS 128
#define TR 4                        // rows per thread
#define TC 8                        // cols per thread
#define LANES 16                    // lane-groups per row (128/TC)
#define CHUNK 32
#define NCHUNK (TT / CHUNK)

// pbuf layout (floats): [step][row][lane], row stride 20 (16B-aligned, padded)
#define PROW 20
#define PSTEP (ROWS * PROW)         // 640

// smem layout (float offsets)
#define SM_XS     0
#define SM_PBUF   (2 * CHUNK * NN)                  // 8192
#define SM_SCOEF  (SM_PBUF + CHUNK * PSTEP)         // +20480 = 28672
#define SM_CSCALE (SM_SCOEF + TT + 2)
#define SM_CFOLD  (SM_CSCALE + TT)
#define SM_APOW   (SM_CFOLD + NCHUNK)
#define SM_APOWI  (SM_APOW + CHUNK + 1)
#define SM_MBITS  (SM_APOWI + CHUNK + 1)
#define SM_FLOATS (SM_MBITS + NCHUNK)
#define SM_BYTES  (SM_FLOATS * 4)                   // ~123.4 KB

typedef unsigned long long u64;

// ---------- packed f32x2 helpers ----------
__device__ __forceinline__ u64 pack2(float lo, float hi) {
    u64 r; asm("mov.b64 %0, {%1, %2};" : "=l"(r) : "f"(lo), "f"(hi)); return r;
}
__device__ __forceinline__ void unpack2(u64 v, float& lo, float& hi) {
    asm("mov.b64 {%0, %1}, %2;" : "=f"(lo), "=f"(hi) : "l"(v));
}
__device__ __forceinline__ u64 fma2(u64 a, u64 b, u64 c) {
    u64 d; asm("fma.rn.f32x2 %0, %1, %2, %3;" : "=l"(d) : "l"(a), "l"(b), "l"(c)); return d;
}
__device__ __forceinline__ u64 mul2(u64 a, u64 b) {
    u64 d; asm("mul.rn.f32x2 %0, %1, %2;" : "=l"(d) : "l"(a), "l"(b)); return d;
}

// ---------- cp.async ----------
__device__ __forceinline__ void cpasync16(void* s, const void* g) {
    unsigned saddr = (unsigned)__cvta_generic_to_shared(s);
    asm volatile("cp.async.cg.shared.global [%0], [%1], 16;" :: "r"(saddr), "l"(g));
}
// 4096 floats per chunk / 128 threads = 32 floats = 8 x 16B each
__device__ __forceinline__ void load_chunk(float* dst, const float* src, int tid) {
    #pragma unroll
    for (int i = 0; i < 8; i++) {
        int off = (tid + i * THREADS) * 4;
        cpasync16(dst + off, src + off);
    }
}

__global__ __launch_bounds__(THREADS, 1)
void bdh_scan_kernel(const float* __restrict__ x,
                     const float* __restrict__ w_init,
                     const float* __restrict__ alpha_p,
                     const float* __restrict__ eta_p,
                     const int*   __restrict__ mask,
                     float* __restrict__ w_out,
                     float* __restrict__ y_out)
{
    extern __shared__ float smem[];
    float*    xs     = smem + SM_XS;
    float*    pbuf   = smem + SM_PBUF;
    float*    scoef  = smem + SM_SCOEF;
    float*    cscale = smem + SM_CSCALE;
    float*    cfold  = smem + SM_CFOLD;
    float*    apow   = smem + SM_APOW;
    float*    apowi  = smem + SM_APOWI;
    unsigned* mbits  = (unsigned*)(smem + SM_MBITS);

    const int b    = blockIdx.x;
    const int rb   = blockIdx.y;
    const int tid  = threadIdx.x;
    const int q    = tid / LANES;          // 0..7 row-group
    const int lane = tid % LANES;          // 0..15
    const int r0l  = q * TR;               // local first row
    const int r0   = rb * ROWS + r0l;      // global first row
    const int cseg = lane * TC;

    const float alpha = alpha_p[0];
    const float eta   = eta_p[0];
    const float inva  = 1.0f / alpha;

    const float* xb = x + (size_t)b * TT * NN;
    float* yb = y_out + (size_t)b * TT * NN;

    // prefetch first two x chunks immediately
    load_chunk(xs, xb, tid);
    asm volatile("cp.async.commit_group;");
    load_chunk(xs + CHUNK * NN, xb + CHUNK * NN, tid);
    asm volatile("cp.async.commit_group;");

    // W tile: 4 rows x 8 cols = 16 packed f32x2
    u64 w2[TR][4];
    {
        const float* wb = w_init + (size_t)b * NN * NN + (size_t)r0 * NN + cseg;
        #pragma unroll
        for (int i = 0; i < TR; i++) {
            const ulonglong2* ws = reinterpret_cast<const ulonglong2*>(wb + i * NN);
            ulonglong2 v0 = ws[0], v1 = ws[1];
            w2[i][0] = v0.x; w2[i][1] = v0.y; w2[i][2] = v1.x; w2[i][3] = v1.y;
        }
    }

    // ---- setup: mask bits + power tables ----
    {
        const int l32 = tid & 31, wi = tid >> 5;
        for (int ckk = wi; ckk < NCHUNK; ckk += 4) {
            int m = mask[(size_t)b * TT + ckk * 32 + l32];
            unsigned bits = __ballot_sync(0xffffffffu, m != 0);
            if (l32 == 0) mbits[ckk] = bits;
        }
    }
    if (tid == 0) {
        float p = 1.0f, pi = 1.0f;
        #pragma unroll
        for (int k = 0; k <= CHUNK; k++) {
            apow[k] = p;  apowi[k] = pi;
            p *= alpha;   pi *= inva;
        }
    }
    __syncthreads();

    // per-step coefficient tables (all chunks, hoisted out of the scan)
    #pragma unroll
    for (int k = 0; k < 8; k++) {
        const int e = tid + k * THREADS;      // 0..1023
        const int ckk = e >> 5, tl = e & 31;
        const unsigned mb = mbits[ckk];
        const int cnt = __popc(mb & ((1u << tl) - 1u));
        cscale[e] = apow[cnt];
        scoef[e]  = ((mb >> tl) & 1u) ? (eta * apowi[cnt + 1]) : 0.0f;
    }
    if (tid < NCHUNK) cfold[tid] = apow[__popc(mbits[tid])];
    if (tid < 2) scoef[TT + tid] = 0.0f;      // over-read pad
    __syncthreads();

    for (int ck = 0; ck < NCHUNK; ck++) {
        asm volatile("cp.async.wait_group 1;");
        __syncthreads();

        const float* xch = xs + (ck & 1) * (CHUNK * NN);
        const float* scp = scoef + ck * CHUNK;

        // ---- software-pipelined, branch-free step loop ----
        ulonglong2 va = reinterpret_cast<const ulonglong2*>(xch + cseg)[0];
        ulonglong2 vb = reinterpret_cast<const ulonglong2*>(xch + cseg)[1];
        float4 xr = *reinterpret_cast<const float4*>(xch + rb * ROWS + r0l);
        float  sc = scp[0];

        #pragma unroll 16
        for (int tl = 0; tl < CHUNK; tl++) {
            const u64 xv0 = va.x, xv1 = va.y, xv2 = vb.x, xv3 = vb.y;
            const float4 xrc = xr;
            const float  scc = sc;

            // prefetch next step (tl==31 over-reads adjacent smem; unused/padded)
            const float* xpn = xch + (tl + 1) * NN;
            va = reinterpret_cast<const ulonglong2*>(xpn + cseg)[0];
            vb = reinterpret_cast<const ulonglong2*>(xpn + cseg)[1];
            xr = *reinterpret_cast<const float4*>(xpn + rb * ROWS + r0l);
            sc = scp[tl + 1];

            // 4 independent dot chains (pre-update W)
            float p[TR];
            #pragma unroll
            for (int i = 0; i < TR; i++) {
                u64 a = mul2(w2[i][0], xv0);
                a = fma2(w2[i][1], xv1, a);
                a = fma2(w2[i][2], xv2, a);
                a = fma2(w2[i][3], xv3, a);
                float lo, hi; unpack2(a, lo, hi);
                p[i] = lo + hi;
            }
            float* pb = pbuf + tl * PSTEP + r0l * PROW + lane;
            pb[0 * PROW] = p[0];
            pb[1 * PROW] = p[1];
            pb[2 * PROW] = p[2];
            pb[3 * PROW] = p[3];

            // branch-free masked update (scc == 0 on unmasked steps)
            const float g0f = scc * xrc.x, g1f = scc * xrc.y;
            const float g2f = scc * xrc.z, g3f = scc * xrc.w;
            const u64 g0 = pack2(g0f, g0f);
            const u64 g1 = pack2(g1f, g1f);
            const u64 g2 = pack2(g2f, g2f);
            const u64 g3 = pack2(g3f, g3f);
            w2[0][0] = fma2(g0, xv0, w2[0][0]);
            w2[0][1] = fma2(g0, xv1, w2[0][1]);
            w2[0][2] = fma2(g0, xv2, w2[0][2]);
            w2[0][3] = fma2(g0, xv3, w2[0][3]);
            w2[1][0] = fma2(g1, xv0, w2[1][0]);
            w2[1][1] = fma2(g1, xv1, w2[1][1]);
            w2[1][2] = fma2(g1, xv2, w2[1][2]);
            w2[1][3] = fma2(g1, xv3, w2[1][3]);
            w2[2][0] = fma2(g2, xv0, w2[2][0]);
            w2[2][1] = fma2(g2, xv1, w2[2][1]);
            w2[2][2] = fma2(g2, xv2, w2[2][2]);
            w2[2][3] = fma2(g2, xv3, w2[2][3]);
            w2[3][0] = fma2(g3, xv0, w2[3][0]);
            w2[3][1] = fma2(g3, xv1, w2[3][1]);
            w2[3][2] = fma2(g3, xv2, w2[3][2]);
            w2[3][3] = fma2(g3, xv3, w2[3][3]);
        }

        // unconditional decay fold (table value; exact)
        {
            const float cf = cfold[ck];
            const u64 c2 = pack2(cf, cf);
            #pragma unroll
            for (int i = 0; i < TR; i++)
                #pragma unroll
                for (int k = 0; k < 4; k++) w2[i][k] = mul2(w2[i][k], c2);
        }

        __syncthreads();   // partials visible; x buffer free

        const int nk = ck + 2;
        if (nk < NCHUNK)
            load_chunk(xs + (ck & 1) * (CHUNK * NN), xb + (size_t)nk * CHUNK * NN, tid);
        asm volatile("cp.async.commit_group;");

        // ---- bulk reduction: 1024 outputs, 8 per thread, float4 loads ----
        #pragma unroll
        for (int o = 0; o < 8; o++) {
            const int id = tid + o * THREADS;
            const int s  = id >> 5;           // step in chunk
            const int r  = id & 31;           // local row
            const float4* pp = reinterpret_cast<const float4*>(
                pbuf + s * PSTEP + r * PROW);
            float4 v0 = pp[0], v1 = pp[1], v2 = pp[2], v3 = pp[3];
            float s0 = (v0.x + v0.y) + (v0.z + v0.w);
            float s1 = (v1.x + v1.y) + (v1.z + v1.w);
            float s2 = (v2.x + v2.y) + (v2.z + v2.w);
            float s3 = (v3.x + v3.y) + (v3.z + v3.w);
            const float sum = (s0 + s1) + (s2 + s3);
            yb[(size_t)(ck * CHUNK + s) * NN + rb * ROWS + r] =
                sum * cscale[ck * CHUNK + s];
        }
        // next top __syncthreads orders pbuf reads before overwrite
    }

    // ---- final W ----
    {
        float* wb = w_out + (size_t)b * NN * NN + (size_t)r0 * NN + cseg;
        #pragma unroll
        for (int i = 0; i < TR; i++) {
            ulonglong2 v0, v1;
            v0.x = w2[i][0]; v0.y = w2[i][1];
            v1.x = w2[i][2]; v1.y = w2[i][3];
            reinterpret_cast<ulonglong2*>(wb + i * NN)[0] = v0;
            reinterpret_cast<ulonglong2*>(wb + i * NN)[1] = v1;
        }
    }
}

extern "C" void kernel_launch(void* const* d_in, const int* in_sizes, int n_in,
                              void* d_out, int out_size) {
    const float* x      = (const float*)d_in[0];
    const float* w_init = (const float*)d_in[1];
    const float* alpha  = (const float*)d_in[2];
    const float* eta    = (const float*)d_in[3];
    const int*   mask   = (const int*)d_in[4];

    float* w_out = (float*)d_out;
    float* y_out = (float*)d_out + (size_t)BB * NN * NN;

    static bool attr_set = false;
    if (!attr_set) {
        cudaFuncSetAttribute(bdh_scan_kernel,
                             cudaFuncAttributeMaxDynamicSharedMemorySize, SM_BYTES);
        attr_set = true;
    }

    dim3 grid(BB, RBLK);
    bdh_scan_kernel<<<grid, THREADS, SM_BYTES>>>(x, w_init, alpha, eta, mask,
                                                 w_out, y_out);
}